// round 1
// baseline (speedup 1.0000x reference)
#include <cuda_runtime.h>
#include <cuda_bf16.h>
#include <math.h>

// Problem constants
#define S    2048
#define D    2048
#define NH   32
#define NKV  8
#define HD   64
#define QKV_N 3072   // (32 + 16) * 64

// ---------------------------------------------------------------------------
// Scratch (device globals — no allocation allowed)
// ---------------------------------------------------------------------------
__device__ float g_qkv[(size_t)S * QKV_N];      // [s, 3072]
__device__ float g_q[(size_t)NH * S * HD];      // [h, s, d]
__device__ float g_k[(size_t)NKV * S * HD];     // [kh, s, d]
__device__ float g_v[(size_t)NKV * S * HD];     // [kh, s, d]
__device__ float g_attn[(size_t)S * D];         // [s, h*64+d]

// ---------------------------------------------------------------------------
// GEMM: C[M,N] = A[M,K] @ B[N,K]^T   (both operands K-major / row-major)
// 128x128 tile, BK=16, 256 threads, 8x8 micro-tile per thread (strided by 16
// for conflict-free shared loads).
// ---------------------------------------------------------------------------
__global__ __launch_bounds__(256) void gemm_nt(const float* __restrict__ A,
                                               const float* __restrict__ B,
                                               float* __restrict__ C,
                                               int M, int N, int K) {
    __shared__ float As[16][128];
    __shared__ float Bs[16][128];

    const int tid = threadIdx.x;
    const int tr  = tid / 16;          // 0..15
    const int tc  = tid % 16;          // 0..15
    const int rowA0 = blockIdx.y * 128;
    const int colB0 = blockIdx.x * 128;

    float acc[8][8];
#pragma unroll
    for (int i = 0; i < 8; i++)
#pragma unroll
        for (int j = 0; j < 8; j++) acc[i][j] = 0.f;

    const int lrow = tid >> 2;          // 0..63
    const int lcol = (tid & 3) * 4;     // 0,4,8,12

    for (int k0 = 0; k0 < K; k0 += 16) {
#pragma unroll
        for (int i = 0; i < 2; i++) {
            int r = lrow + i * 64;
            float4 va = *(const float4*)&A[(size_t)(rowA0 + r) * K + k0 + lcol];
            As[lcol + 0][r] = va.x; As[lcol + 1][r] = va.y;
            As[lcol + 2][r] = va.z; As[lcol + 3][r] = va.w;
            float4 vb = *(const float4*)&B[(size_t)(colB0 + r) * K + k0 + lcol];
            Bs[lcol + 0][r] = vb.x; Bs[lcol + 1][r] = vb.y;
            Bs[lcol + 2][r] = vb.z; Bs[lcol + 3][r] = vb.w;
        }
        __syncthreads();

#pragma unroll
        for (int kk = 0; kk < 16; kk++) {
            float a[8], b[8];
#pragma unroll
            for (int i = 0; i < 8; i++) a[i] = As[kk][tr + i * 16];
#pragma unroll
            for (int j = 0; j < 8; j++) b[j] = Bs[kk][tc + j * 16];
#pragma unroll
            for (int i = 0; i < 8; i++)
#pragma unroll
                for (int j = 0; j < 8; j++) acc[i][j] += a[i] * b[j];
        }
        __syncthreads();
    }

#pragma unroll
    for (int i = 0; i < 8; i++) {
        int r = rowA0 + tr + i * 16;
#pragma unroll
        for (int j = 0; j < 8; j++)
            C[(size_t)r * N + colB0 + tc + j * 16] = acc[i][j];
    }
}

// ---------------------------------------------------------------------------
// RoPE on Q and K, scatter to [head, seq, hd]; V copied to [kh, seq, hd].
// freqs_cis layout: [s, HD/2, 2] -> fc[s*64 + 2*d2 + {0:cos,1:sin}]
// ---------------------------------------------------------------------------
__global__ __launch_bounds__(256) void rope_scatter(const float* __restrict__ qkv,
                                                    const float* __restrict__ fc,
                                                    float* __restrict__ Qo,
                                                    float* __restrict__ Ko,
                                                    float* __restrict__ Vo) {
    const int s   = blockIdx.x;
    const int tid = threadIdx.x;
    const float* row = qkv + (size_t)s * QKV_N;

    // Q: 32 heads * 32 pairs
    for (int i = tid; i < NH * (HD / 2); i += 256) {
        int h = i >> 5, d2 = i & 31;
        float x0 = row[h * HD + 2 * d2];
        float x1 = row[h * HD + 2 * d2 + 1];
        float c  = fc[s * HD + 2 * d2];
        float sn = fc[s * HD + 2 * d2 + 1];
        float* dst = Qo + ((size_t)h * S + s) * HD + 2 * d2;
        dst[0] = x0 * c - x1 * sn;
        dst[1] = x1 * c + x0 * sn;
    }
    // K: 8 heads * 32 pairs = 256 items, one per thread
    {
        int h = tid >> 5, d2 = tid & 31;
        float x0 = row[D + h * HD + 2 * d2];
        float x1 = row[D + h * HD + 2 * d2 + 1];
        float c  = fc[s * HD + 2 * d2];
        float sn = fc[s * HD + 2 * d2 + 1];
        float* dst = Ko + ((size_t)h * S + s) * HD + 2 * d2;
        dst[0] = x0 * c - x1 * sn;
        dst[1] = x1 * c + x0 * sn;
    }
    // V: 512 floats
    for (int i = tid; i < NKV * HD; i += 256) {
        int h = i >> 6, d = i & 63;
        Vo[((size_t)h * S + s) * HD + d] = row[D + NKV * HD + i];
    }
}

// ---------------------------------------------------------------------------
// Causal flash attention (fp32). One thread per query row, BQ=128 rows/block,
// TK=32 kv rows per shared tile. Online softmax, scores kept in registers.
// Output written in [s, h*HD + d] layout for the final projection GEMM.
// ---------------------------------------------------------------------------
#define BQ 128
#define TK 32

__global__ __launch_bounds__(BQ) void flash_attn(const float* __restrict__ Qm,
                                                 const float* __restrict__ Km,
                                                 const float* __restrict__ Vm,
                                                 float* __restrict__ O) {
    __shared__ float Ks[TK][HD];
    __shared__ float Vs[TK][HD];

    const int h   = blockIdx.y;
    const int kh  = h >> 2;            // GQA: 4 q-heads per kv-head
    const int qb  = blockIdx.x;
    const int tid = threadIdx.x;
    const int qi  = qb * BQ + tid;

    float q[HD], acc[HD];
#pragma unroll
    for (int d = 0; d < HD; d++) {
        q[d]   = Qm[((size_t)h * S + qi) * HD + d];
        acc[d] = 0.f;
    }
    float m = -1e30f, l = 0.f;

    const int kv_end = (qb + 1) * BQ;
    for (int kv0 = 0; kv0 < kv_end; kv0 += TK) {
        // cooperative load of K/V tiles: 32x64 floats each -> 4 float4 per thread
#pragma unroll
        for (int i = 0; i < 4; i++) {
            int idx = tid + i * BQ;           // float4 index 0..511
            int r = idx >> 4, c4 = (idx & 15) * 4;
            *(float4*)&Ks[r][c4] =
                *(const float4*)&Km[((size_t)kh * S + kv0 + r) * HD + c4];
            *(float4*)&Vs[r][c4] =
                *(const float4*)&Vm[((size_t)kh * S + kv0 + r) * HD + c4];
        }
        __syncthreads();

        float sreg[TK];
        float tmax = -1e30f;
#pragma unroll
        for (int j = 0; j < TK; j++) {
            float sv = 0.f;
#pragma unroll
            for (int d = 0; d < HD; d++) sv += q[d] * Ks[j][d];
            sv *= 0.125f;                       // 1/sqrt(64)
            if (kv0 + j > qi) sv = -1e30f;      // causal mask
            sreg[j] = sv;
            tmax = fmaxf(tmax, sv);
        }
        float mnew  = fmaxf(m, tmax);
        float scale = expf(m - mnew);
        l *= scale;
#pragma unroll
        for (int d = 0; d < HD; d++) acc[d] *= scale;
#pragma unroll
        for (int j = 0; j < TK; j++) {
            float p = expf(sreg[j] - mnew);
            l += p;
#pragma unroll
            for (int d = 0; d < HD; d++) acc[d] += p * Vs[j][d];
        }
        m = mnew;
        __syncthreads();
    }

    float inv = 1.f / l;
#pragma unroll
    for (int d = 0; d < HD; d++)
        O[(size_t)qi * D + h * HD + d] = acc[d] * inv;
}

// ---------------------------------------------------------------------------
// Launch
// ---------------------------------------------------------------------------
extern "C" void kernel_launch(void* const* d_in, const int* in_sizes, int n_in,
                              void* d_out, int out_size) {
    const float* hs   = (const float*)d_in[0];   // [1, 2048, 2048]
    const float* fc   = (const float*)d_in[1];   // [2048, 32, 2]
    const float* wqkv = (const float*)d_in[2];   // [3072, 2048]
    const float* wo   = (const float*)d_in[3];   // [2048, 2048]
    float* out = (float*)d_out;                  // [1, 2048, 2048]

    float *p_qkv, *p_q, *p_k, *p_v, *p_attn;
    cudaGetSymbolAddress((void**)&p_qkv,  g_qkv);
    cudaGetSymbolAddress((void**)&p_q,    g_q);
    cudaGetSymbolAddress((void**)&p_k,    g_k);
    cudaGetSymbolAddress((void**)&p_v,    g_v);
    cudaGetSymbolAddress((void**)&p_attn, g_attn);

    // 1) qkv = hs @ wqkv^T : M=2048, N=3072, K=2048
    gemm_nt<<<dim3(QKV_N / 128, S / 128), 256>>>(hs, wqkv, p_qkv, S, QKV_N, D);

    // 2) RoPE + scatter to head-major
    rope_scatter<<<S, 256>>>(p_qkv, fc, p_q, p_k, p_v);

    // 3) causal attention
    flash_attn<<<dim3(S / BQ, NH), BQ>>>(p_q, p_k, p_v, p_attn);

    // 4) out = attn @ wo^T : M=N=K=2048
    gemm_nt<<<dim3(D / 128, S / 128), 256>>>(p_attn, wo, out, S, D, D);
}